// round 12
// baseline (speedup 1.0000x reference)
#include <cuda_runtime.h>
#include <cstdint>

#define NB 4
#define NS 2048
#define ND 128
#define NDL 16
#define NTOP 8

#define NSEG 64
#define QSEG (NS / NSEG)   // 32

#define KSPLIT 4
#define KPART (NS / KSPLIT)   // 512

typedef unsigned long long ull;

// ---- scratch (device globals; no allocation allowed) ----
__device__ float g_qlow[NB * NS * NDL];
__device__ float g_klow[NB * NS * NDL];
__device__ float g_sh[NB * NS];
__device__ float g_S[(size_t)NB * NS * NS];          // corrected scores (topk/colpart only)
__device__ float g_psum[NSEG * NB * NS];             // column partial sums
__device__ float g_cinv[NB * NS];
__device__ int   g_tidx[NB * NS * NTOP];             // top-8 indices per row
__device__ float g_po[KSPLIT][NB * NS * ND];         // split-k partial outputs

__device__ __forceinline__ float neg_inf() { return __int_as_float(0xff800000u); }

// ---- packed f32x2 helpers (FFMA2 path; ptxas won't emit this from C++) ----
__device__ __forceinline__ ull pack2(float lo, float hi) {
    ull r;
    asm("mov.b64 %0, {%1, %2};" : "=l"(r) : "f"(lo), "f"(hi));
    return r;
}
__device__ __forceinline__ ull pack2dup(float v) {
    ull r;
    asm("mov.b64 %0, {%1, %1};" : "=l"(r) : "f"(v));
    return r;
}
__device__ __forceinline__ void unpack2(ull v, float& lo, float& hi) {
    asm("mov.b64 {%0, %1}, %2;" : "=f"(lo), "=f"(hi) : "l"(v));
}
__device__ __forceinline__ void fma2(ull& acc, ull a, ull b) {
    asm("fma.rn.f32x2 %0, %1, %2, %0;" : "+l"(acc) : "l"(a), "l"(b));
}

// ============================================================
// K1: low/high projections + per-(b,k) correction scalar sh
// ============================================================
__global__ void __launch_bounds__(64) k_proj(
    const float* __restrict__ Q, const float* __restrict__ K,
    const float* __restrict__ Wql, const float* __restrict__ bql,
    const float* __restrict__ Wkl, const float* __restrict__ bkl,
    const float* __restrict__ Wqh, const float* __restrict__ bqh,
    const float* __restrict__ Wkh, const float* __restrict__ bkh)
{
    int row = blockIdx.x;          // b*NS + i
    int t = threadIdx.x;
    __shared__ float qr[ND];
    __shared__ float kr[ND];
    __shared__ float qh[NDL];
    __shared__ float kh[NDL];

    qr[t]      = Q[(size_t)row * ND + t];
    qr[t + 64] = Q[(size_t)row * ND + t + 64];
    kr[t]      = K[(size_t)row * ND + t];
    kr[t + 64] = K[(size_t)row * ND + t + 64];
    __syncthreads();

    int g = t >> 4, j = t & 15;
    if (g == 0) {
        float a = bql[j];
        #pragma unroll 8
        for (int e = 0; e < ND; e++) a += qr[e] * Wql[e * NDL + j];
        g_qlow[(size_t)row * NDL + j] = a;
    } else if (g == 1) {
        float a = bkl[j];
        #pragma unroll 8
        for (int e = 0; e < ND; e++) a += kr[e] * Wkl[e * NDL + j];
        g_klow[(size_t)row * NDL + j] = a;
    } else if (g == 2) {
        float a = bqh[j];
        #pragma unroll 8
        for (int e = 0; e < ND; e++) a += qr[e] * Wqh[e * NDL + j];
        qh[j] = a;
    } else {
        float a = bkh[j];
        #pragma unroll 8
        for (int e = 0; e < ND; e++) a += kr[e] * Wkh[e * NDL + j];
        kh[j] = a;
    }
    __syncthreads();

    if (t == 0) {
        float s = 0.f;
        #pragma unroll
        for (int j2 = 0; j2 < NDL; j2++) s += qh[j2] * kh[j2];
        g_sh[row] = 0.25f * s;    // scale = 1/sqrt(16)
    }
}

// ============================================================
// K2a: masked low-rank scores -> g_S  (f32x2 packed: 2 q rows per lane)
// ============================================================
__global__ void __launch_bounds__(256) k_scores(const int* __restrict__ VL)
{
    __shared__ __align__(16) float ks[128][20];
    __shared__ __align__(16) float Ss[32][132];
    __shared__ int vls[128];

    int b  = blockIdx.z;
    int q0 = blockIdx.y * 32;
    int k0 = blockIdx.x * 128;
    int t  = threadIdx.x;

    {
        const float4* src = (const float4*)(g_klow + ((size_t)b * NS + k0) * NDL);
        #pragma unroll
        for (int u = 0; u < 2; u++) {
            int p = t + u * 256;
            float4 v = src[p];
            *(float4*)&ks[p >> 2][(p & 3) * 4] = v;
        }
    }
    if (t < 128) {
        int vlc = VL[b * NS + k0 + t];
        vlc = vlc < 0 ? 0 : (vlc > NS - 1 ? NS - 1 : vlc);
        vls[t] = vlc;
    }
    __syncthreads();

    int tq = t >> 4;             // 0..15
    int kg = t & 15;             // 0..15
    int ql0 = tq * 2;
    int qg0 = q0 + ql0, qg1 = qg0 + 1;

    ull qp2[NDL];
    {
        const float4* qp = (const float4*)(g_qlow + ((size_t)b * NS + qg0) * NDL);
        #pragma unroll
        for (int u = 0; u < 4; u++) {
            float4 v = qp[u];       // row 0
            float4 w = qp[u + 4];   // row 1
            qp2[u * 4 + 0] = pack2(v.x, w.x);
            qp2[u * 4 + 1] = pack2(v.y, w.y);
            qp2[u * 4 + 2] = pack2(v.z, w.z);
            qp2[u * 4 + 3] = pack2(v.w, w.w);
        }
    }

    #pragma unroll
    for (int i = 0; i < 8; i++) {
        int kl = kg + 16 * i;
        ull acc = 0ull;
        #pragma unroll
        for (int u = 0; u < 4; u++) {
            float4 kv = *(const float4*)&ks[kl][u * 4];
            fma2(acc, qp2[u * 4 + 0], pack2dup(kv.x));
            fma2(acc, qp2[u * 4 + 1], pack2dup(kv.y));
            fma2(acc, qp2[u * 4 + 2], pack2dup(kv.z));
            fma2(acc, qp2[u * 4 + 3], pack2dup(kv.w));
        }
        float a0, a1;
        unpack2(acc, a0, a1);
        a0 *= 0.25f; a1 *= 0.25f;
        int vlc = vls[kl];
        if (vlc == qg0) a0 += -1e9f;
        if (vlc == qg1) a1 += -1e9f;
        Ss[ql0][kl]     = a0;
        Ss[ql0 + 1][kl] = a1;
    }
    __syncthreads();

    #pragma unroll
    for (int u = 0; u < 4; u++) {
        int p = t + u * 256;
        int row = p >> 5, cg = p & 31;
        float4 v = *(const float4*)&Ss[row][cg * 4];
        *(float4*)(g_S + ((size_t)b * NS + q0 + row) * NS + k0 + cg * 4) = v;
    }
}

// ============================================================
// K2b: per-row top-8 and scatter sh into g_S; stores indices for k_fix
// ============================================================
__global__ void __launch_bounds__(256) k_topk()
{
    int q = blockIdx.x, b = blockIdx.y;
    int t = threadIdx.x;
    __shared__ __align__(16) float wk[NS];
    __shared__ float rv[8];
    __shared__ int ri[8];
    __shared__ int s_mi;
    __shared__ int topIdx[NTOP];

    float* Srow = g_S + ((size_t)b * NS + q) * NS;
    #pragma unroll
    for (int u = 0; u < 2; u++) {
        int p = t + u * 256;
        ((float4*)wk)[p] = ((const float4*)Srow)[p];
    }
    __syncthreads();

    float lv = neg_inf(); int li = 0;
    #pragma unroll
    for (int i = 0; i < 8; i++) {
        int k = t + i * 256;
        float v = wk[k];
        if (v > lv) { lv = v; li = k; }
    }

    for (int r = 0; r < NTOP; r++) {
        float mv = lv; int mi = li;
        #pragma unroll
        for (int o = 16; o > 0; o >>= 1) {
            float ov = __shfl_xor_sync(0xffffffffu, mv, o);
            int   oi = __shfl_xor_sync(0xffffffffu, mi, o);
            if (ov > mv || (ov == mv && oi < mi)) { mv = ov; mi = oi; }
        }
        if ((t & 31) == 0) { rv[t >> 5] = mv; ri[t >> 5] = mi; }
        __syncthreads();
        if (t == 0) {
            #pragma unroll
            for (int w = 1; w < 8; w++)
                if (rv[w] > mv || (rv[w] == mv && ri[w] < mi)) { mv = rv[w]; mi = ri[w]; }
            topIdx[r] = mi;
            s_mi = mi;
        }
        __syncthreads();
        if (r < NTOP - 1) {
            int gm = s_mi;
            if ((gm & 255) == t) {      // only the owner rescans
                wk[gm] = neg_inf();
                lv = neg_inf(); li = 0;
                #pragma unroll
                for (int i = 0; i < 8; i++) {
                    int k = t + i * 256;
                    float v = wk[k];
                    if (v > lv) { lv = v; li = k; }
                }
            }
        }
    }

    if (t < NTOP) {
        int idx = topIdx[t];
        Srow[idx] = g_sh[b * NS + idx];
        g_tidx[(b * NS + q) * NTOP + t] = idx;
    }
}

// ============================================================
// K3a: partial column sum of exp over q-segments (round-6 version)
// ============================================================
__global__ void __launch_bounds__(256) k_colpart()
{
    int k  = (blockIdx.x * 256 + threadIdx.x) * 4;
    int b  = blockIdx.y;
    int seg = blockIdx.z;
    const float* Sb = g_S + (size_t)b * NS * NS;
    int q0 = seg * QSEG;

    float4 s = make_float4(0.f, 0.f, 0.f, 0.f);
    #pragma unroll 4
    for (int q = q0; q < q0 + QSEG; q++) {
        float4 v = *(const float4*)&Sb[(size_t)q * NS + k];
        s.x += __expf(v.x);
        s.y += __expf(v.y);
        s.z += __expf(v.z);
        s.w += __expf(v.w);
    }
    *(float4*)&g_psum[((size_t)seg * NB + b) * NS + k] = s;
}

// K3b: combine segments -> 1/colsum
__global__ void __launch_bounds__(256) k_colfin()
{
    int i = blockIdx.x * 256 + threadIdx.x;   // b*NS + k
    float s = 0.f;
    #pragma unroll 8
    for (int seg = 0; seg < NSEG; seg++)
        s += g_psum[(size_t)seg * (NB * NS) + i];
    g_cinv[i] = 1.0f / s;
}

// ============================================================
// K4: RECOMPUTE k_out. No E read — A-tile recomputed from
// qlow (regs) x klow (smem), exact same FMA order as k_scores,
// masked, exp'd, *cinv, dup-packed to smem. Then FFMA2 GEMM vs V.
// grid (NS/64, NB, KSPLIT); block 256; tile 64q x 128d; chunk 32k.
// Uncorrected at top-8 entries; k_fix patches output sparsely.
// ============================================================
__global__ void __launch_bounds__(256, 2) k_out(const float* __restrict__ V,
                                                const int* __restrict__ VL)
{
    __shared__ ull As2[64][36];                      // 18 KB dup-packed A
    __shared__ __align__(16) float Vs[32][128];      // 16 KB
    __shared__ __align__(16) float kls[32][20];      // klow chunk
    __shared__ int   vls[32];
    __shared__ float cis[32];

    int b  = blockIdx.y;
    int q0 = blockIdx.x * 64;
    int z  = blockIdx.z;
    int t  = threadIdx.x;
    int tx = t & 31;     // d group: d = tx*4
    int ty = t >> 5;     // q group: q = q0 + ty*8 + qq

    const float* Vb = V + (size_t)b * NS * ND;

    // A-compute mapping: rows rA = t>>3 and rA+32; cols (t&7)*4 .. +3
    int rA = t >> 3;
    int cg4 = (t & 7) * 4;
    int qA = q0 + rA, qB = qA + 32;

    // qlow rows for rA and rA+32, packed (rowA, rowB) — loaded once (L2)
    ull qp2[NDL];
    {
        const float4* qa = (const float4*)(g_qlow + ((size_t)b * NS + qA) * NDL);
        const float4* qb = (const float4*)(g_qlow + ((size_t)b * NS + qB) * NDL);
        #pragma unroll
        for (int u = 0; u < 4; u++) {
            float4 v = qa[u];
            float4 w = qb[u];
            qp2[u * 4 + 0] = pack2(v.x, w.x);
            qp2[u * 4 + 1] = pack2(v.y, w.y);
            qp2[u * 4 + 2] = pack2(v.z, w.z);
            qp2[u * 4 + 3] = pack2(v.w, w.w);
        }
    }

    ull acc2[8][2];
    #pragma unroll
    for (int i = 0; i < 8; i++) { acc2[i][0] = 0ull; acc2[i][1] = 0ull; }

    int kbeg = z * KPART, kend = kbeg + KPART;
    for (int k0 = kbeg; k0 < kend; k0 += 32) {
        __syncthreads();
        // ---- stage klow chunk [32][16] (128 float4), vls, cinv, V tile ----
        if (t < 128) {
            float4 v = ((const float4*)(g_klow + ((size_t)b * NS + k0) * NDL))[t];
            *(float4*)&kls[t >> 2][(t & 3) * 4] = v;
        }
        if (t >= 128 && t < 160) {
            int kk = t - 128;
            int vlc = VL[b * NS + k0 + kk];
            vlc = vlc < 0 ? 0 : (vlc > NS - 1 ? NS - 1 : vlc);
            vls[kk] = vlc;
            cis[kk] = g_cinv[b * NS + k0 + kk];
        }
        #pragma unroll
        for (int u = 0; u < 4; u++) {
            int p = t + u * 256;
            int row = p >> 5, colg = p & 31;
            *(float4*)&Vs[row][colg * 4] =
                *(const float4*)&Vb[(size_t)(k0 + row) * ND + colg * 4];
        }
        __syncthreads();

        // ---- compute A: 2 rows x 4 cols per thread, exact k_scores order ----
        #pragma unroll
        for (int c = 0; c < 4; c++) {
            int kl = cg4 + c;
            ull acc = 0ull;
            #pragma unroll
            for (int u = 0; u < 4; u++) {
                float4 kv = *(const float4*)&kls[kl][u * 4];
                fma2(acc, qp2[u * 4 + 0], pack2dup(kv.x));
                fma2(acc, qp2[u * 4 + 1], pack2dup(kv.y));
                fma2(acc, qp2[u * 4 + 2], pack2dup(kv.z));
                fma2(acc, qp2[u * 4 + 3], pack2dup(kv.w));
            }
            float a0, a1;
            unpack2(acc, a0, a1);
            a0 *= 0.25f; a1 *= 0.25f;
            int vlc = vls[kl];
            if (vlc == qA) a0 += -1e9f;
            if (vlc == qB) a1 += -1e9f;
            float ci = cis[kl];
            As2[rA][kl]      = pack2dup(__expf(a0) * ci);
            As2[rA + 32][kl] = pack2dup(__expf(a1) * ci);
        }
        __syncthreads();

        // ---- main FFMA2 GEMM ----
        #pragma unroll
        for (int kk = 0; kk < 32; kk++) {
            ulonglong2 vv = *(const ulonglong2*)&Vs[kk][tx * 4];
            #pragma unroll
            for (int qq = 0; qq < 8; qq++) {
                ull aa = As2[ty * 8 + qq][kk];   // LDS64 broadcast
                fma2(acc2[qq][0], aa, vv.x);
                fma2(acc2[qq][1], aa, vv.y);
            }
        }
    }

    float* po = g_po[z];
    #pragma unroll
    for (int qq = 0; qq < 8; qq++) {
        float4 o;
        unpack2(acc2[qq][0], o.x, o.y);
        unpack2(acc2[qq][1], o.z, o.w);
        *(float4*)&po[(size_t)((b * NS) + q0 + ty * 8 + qq) * ND + tx * 4] = o;
    }
}

// K5: add split-k partials -> final out
__global__ void __launch_bounds__(256) k_add(float* __restrict__ Out)
{
    int p = blockIdx.x * 256 + threadIdx.x;   // float4 index
    float4 a = ((const float4*)g_po[0])[p];
    #pragma unroll
    for (int z = 1; z < KSPLIT; z++) {
        float4 c = ((const float4*)g_po[z])[p];
        a.x += c.x; a.y += c.y; a.z += c.z; a.w += c.w;
    }
    ((float4*)Out)[p] = a;
}

// ============================================================
// K6: sparse top-8 correction: out[q,:] += (exp(sh)-Etilde)*cinv*V[idx,:]
// one warp per row; grid (NS/8, NB), block 256.
// Etilde recomputed with identical scalar FMA order -> exact.
// ============================================================
__global__ void __launch_bounds__(256) k_fix(const float* __restrict__ V,
                                             const int* __restrict__ VL,
                                             float* __restrict__ Out)
{
    int b = blockIdx.y;
    int q = blockIdx.x * 8 + (threadIdx.x >> 5);
    int lane = threadIdx.x & 31;

    float delta = 0.f;
    int myidx = 0;
    if (lane < NTOP) {
        myidx = g_tidx[(b * NS + q) * NTOP + lane];
        // recompute uncorrected masked score (same rounding as fma2 chain)
        const float* qr = g_qlow + ((size_t)b * NS + q) * NDL;
        const float* kr = g_klow + ((size_t)b * NS + myidx) * NDL;
        float s = 0.f;
        #pragma unroll
        for (int e = 0; e < NDL; e++) s = fmaf(qr[e], kr[e], s);
        s *= 0.25f;
        int vlc = VL[b * NS + myidx];
        vlc = vlc < 0 ? 0 : (vlc > NS - 1 ? NS - 1 : vlc);
        if (vlc == q) s += -1e9f;
        float et = __expf(s);
        float ec = __expf(g_sh[b * NS + myidx]);
        delta = (ec - et) * g_cinv[b * NS + myidx];
    }

    const float* Vb = V + (size_t)b * NS * ND;
    float4 o = make_float4(0.f, 0.f, 0.f, 0.f);
    #pragma unroll
    for (int r = 0; r < NTOP; r++) {
        float dr  = __shfl_sync(0xffffffffu, delta, r);
        int   ir  = __shfl_sync(0xffffffffu, myidx, r);
        float4 v = *(const float4*)&Vb[(size_t)ir * ND + lane * 4];
        o.x = fmaf(dr, v.x, o.x);
        o.y = fmaf(dr, v.y, o.y);
        o.z = fmaf(dr, v.z, o.z);
        o.w = fmaf(dr, v.w, o.w);
    }
    float* op = &Out[(size_t)(b * NS + q) * ND + lane * 4];
    float4 cur = *(const float4*)op;
    cur.x += o.x; cur.y += o.y; cur.z += o.z; cur.w += o.w;
    *(float4*)op = cur;
}

// ============================================================
extern "C" void kernel_launch(void* const* d_in, const int* in_sizes, int n_in,
                              void* d_out, int out_size)
{
    const float* Q   = (const float*)d_in[0];
    const float* K   = (const float*)d_in[1];
    const float* V   = (const float*)d_in[2];
    const int*   VL  = (const int*)d_in[3];
    const float* Wql = (const float*)d_in[4];
    const float* bql = (const float*)d_in[5];
    const float* Wkl = (const float*)d_in[6];
    const float* bkl = (const float*)d_in[7];
    const float* Wqh = (const float*)d_in[8];
    const float* bqh = (const float*)d_in[9];
    const float* Wkh = (const float*)d_in[10];
    const float* bkh = (const float*)d_in[11];
    float* out = (float*)d_out;

    k_proj<<<NB * NS, 64>>>(Q, K, Wql, bql, Wkl, bkl, Wqh, bqh, Wkh, bkh);

    dim3 g2(NS / 128, NS / 32, NB);
    k_scores<<<g2, 256>>>(VL);

    dim3 g2b(NS, NB);
    k_topk<<<g2b, 256>>>();

    dim3 g3(2, NB, NSEG);
    k_colpart<<<g3, 256>>>();
    k_colfin<<<(NB * NS) / 256, 256>>>();

    dim3 g4(NS / 64, NB, KSPLIT);
    k_out<<<g4, 256>>>(V, VL);

    k_add<<<(NB * NS * ND) / 4 / 256, 256>>>(out);

    dim3 g6(NS / 8, NB);
    k_fix<<<g6, 256>>>(V, VL, out);
}

// round 13
// speedup vs baseline: 1.1837x; 1.1837x over previous
#include <cuda_runtime.h>
#include <cstdint>

#define NB 4
#define NS 2048
#define ND 128
#define NDL 16
#define NTOP 8

#define NSEG 64
#define QSEG (NS / NSEG)   // 32

#define KSPLIT 4
#define KPART (NS / KSPLIT)   // 512
#define KC 32

typedef unsigned long long ull;

// ---- scratch (device globals; no allocation allowed) ----
__device__ float g_qlow[NB * NS * NDL];
__device__ float g_klow[NB * NS * NDL];
__device__ float g_sh[NB * NS];
__device__ float g_S[(size_t)NB * NS * NS];          // 64 MB corrected scores
__device__ float g_psum[NSEG * NB * NS];             // column partial sums
__device__ float g_cinv[NB * NS];
__device__ float g_po[KSPLIT][NB * NS * ND];         // split-k partial outputs

__device__ __forceinline__ float neg_inf() { return __int_as_float(0xff800000u); }

// ---- packed f32x2 helpers (FFMA2 path; ptxas won't emit this from C++) ----
__device__ __forceinline__ ull pack2(float lo, float hi) {
    ull r;
    asm("mov.b64 %0, {%1, %2};" : "=l"(r) : "f"(lo), "f"(hi));
    return r;
}
__device__ __forceinline__ ull pack2dup(float v) {
    ull r;
    asm("mov.b64 %0, {%1, %1};" : "=l"(r) : "f"(v));
    return r;
}
__device__ __forceinline__ void unpack2(ull v, float& lo, float& hi) {
    asm("mov.b64 {%0, %1}, %2;" : "=f"(lo), "=f"(hi) : "l"(v));
}
__device__ __forceinline__ void fma2(ull& acc, ull a, ull b) {
    asm("fma.rn.f32x2 %0, %1, %2, %0;" : "+l"(acc) : "l"(a), "l"(b));
}

// ============================================================
// K1: low/high projections + per-(b,k) correction scalar sh
// ============================================================
__global__ void __launch_bounds__(64) k_proj(
    const float* __restrict__ Q, const float* __restrict__ K,
    const float* __restrict__ Wql, const float* __restrict__ bql,
    const float* __restrict__ Wkl, const float* __restrict__ bkl,
    const float* __restrict__ Wqh, const float* __restrict__ bqh,
    const float* __restrict__ Wkh, const float* __restrict__ bkh)
{
    int row = blockIdx.x;          // b*NS + i
    int t = threadIdx.x;
    __shared__ float qr[ND];
    __shared__ float kr[ND];
    __shared__ float qh[NDL];
    __shared__ float kh[NDL];

    qr[t]      = Q[(size_t)row * ND + t];
    qr[t + 64] = Q[(size_t)row * ND + t + 64];
    kr[t]      = K[(size_t)row * ND + t];
    kr[t + 64] = K[(size_t)row * ND + t + 64];
    __syncthreads();

    int g = t >> 4, j = t & 15;
    if (g == 0) {
        float a = bql[j];
        #pragma unroll 8
        for (int e = 0; e < ND; e++) a += qr[e] * Wql[e * NDL + j];
        g_qlow[(size_t)row * NDL + j] = a;
    } else if (g == 1) {
        float a = bkl[j];
        #pragma unroll 8
        for (int e = 0; e < ND; e++) a += kr[e] * Wkl[e * NDL + j];
        g_klow[(size_t)row * NDL + j] = a;
    } else if (g == 2) {
        float a = bqh[j];
        #pragma unroll 8
        for (int e = 0; e < ND; e++) a += qr[e] * Wqh[e * NDL + j];
        qh[j] = a;
    } else {
        float a = bkh[j];
        #pragma unroll 8
        for (int e = 0; e < ND; e++) a += kr[e] * Wkh[e * NDL + j];
        kh[j] = a;
    }
    __syncthreads();

    if (t == 0) {
        float s = 0.f;
        #pragma unroll
        for (int j2 = 0; j2 < NDL; j2++) s += qh[j2] * kh[j2];
        g_sh[row] = 0.25f * s;    // scale = 1/sqrt(16)
    }
}

// ============================================================
// K2a: masked low-rank scores -> g_S  (f32x2 packed: 2 q rows per lane)
// ============================================================
__global__ void __launch_bounds__(256) k_scores(const int* __restrict__ VL)
{
    __shared__ __align__(16) float ks[128][20];
    __shared__ __align__(16) float Ss[32][132];
    __shared__ int vls[128];

    int b  = blockIdx.z;
    int q0 = blockIdx.y * 32;
    int k0 = blockIdx.x * 128;
    int t  = threadIdx.x;

    {
        const float4* src = (const float4*)(g_klow + ((size_t)b * NS + k0) * NDL);
        #pragma unroll
        for (int u = 0; u < 2; u++) {
            int p = t + u * 256;
            float4 v = src[p];
            *(float4*)&ks[p >> 2][(p & 3) * 4] = v;
        }
    }
    if (t < 128) {
        int vlc = VL[b * NS + k0 + t];
        vlc = vlc < 0 ? 0 : (vlc > NS - 1 ? NS - 1 : vlc);
        vls[t] = vlc;
    }
    __syncthreads();

    int tq = t >> 4;             // 0..15
    int kg = t & 15;             // 0..15
    int ql0 = tq * 2;
    int qg0 = q0 + ql0, qg1 = qg0 + 1;

    ull qp2[NDL];
    {
        const float4* qp = (const float4*)(g_qlow + ((size_t)b * NS + qg0) * NDL);
        #pragma unroll
        for (int u = 0; u < 4; u++) {
            float4 v = qp[u];       // row 0
            float4 w = qp[u + 4];   // row 1
            qp2[u * 4 + 0] = pack2(v.x, w.x);
            qp2[u * 4 + 1] = pack2(v.y, w.y);
            qp2[u * 4 + 2] = pack2(v.z, w.z);
            qp2[u * 4 + 3] = pack2(v.w, w.w);
        }
    }

    #pragma unroll
    for (int i = 0; i < 8; i++) {
        int kl = kg + 16 * i;
        ull acc = 0ull;
        #pragma unroll
        for (int u = 0; u < 4; u++) {
            float4 kv = *(const float4*)&ks[kl][u * 4];
            fma2(acc, qp2[u * 4 + 0], pack2dup(kv.x));
            fma2(acc, qp2[u * 4 + 1], pack2dup(kv.y));
            fma2(acc, qp2[u * 4 + 2], pack2dup(kv.z));
            fma2(acc, qp2[u * 4 + 3], pack2dup(kv.w));
        }
        float a0, a1;
        unpack2(acc, a0, a1);
        a0 *= 0.25f; a1 *= 0.25f;
        int vlc = vls[kl];
        if (vlc == qg0) a0 += -1e9f;
        if (vlc == qg1) a1 += -1e9f;
        Ss[ql0][kl]     = a0;
        Ss[ql0 + 1][kl] = a1;
    }
    __syncthreads();

    #pragma unroll
    for (int u = 0; u < 4; u++) {
        int p = t + u * 256;
        int row = p >> 5, cg = p & 31;
        float4 v = *(const float4*)&Ss[row][cg * 4];
        *(float4*)(g_S + ((size_t)b * NS + q0 + row) * NS + k0 + cg * 4) = v;
    }
}

// ============================================================
// K2b: per-row top-8 and scatter sh into g_S
// ============================================================
__global__ void __launch_bounds__(256) k_topk()
{
    int q = blockIdx.x, b = blockIdx.y;
    int t = threadIdx.x;
    __shared__ __align__(16) float wk[NS];
    __shared__ float rv[8];
    __shared__ int ri[8];
    __shared__ int s_mi;
    __shared__ int topIdx[NTOP];

    float* Srow = g_S + ((size_t)b * NS + q) * NS;
    #pragma unroll
    for (int u = 0; u < 2; u++) {
        int p = t + u * 256;
        ((float4*)wk)[p] = ((const float4*)Srow)[p];
    }
    __syncthreads();

    float lv = neg_inf(); int li = 0;
    #pragma unroll
    for (int i = 0; i < 8; i++) {
        int k = t + i * 256;
        float v = wk[k];
        if (v > lv) { lv = v; li = k; }
    }

    for (int r = 0; r < NTOP; r++) {
        float mv = lv; int mi = li;
        #pragma unroll
        for (int o = 16; o > 0; o >>= 1) {
            float ov = __shfl_xor_sync(0xffffffffu, mv, o);
            int   oi = __shfl_xor_sync(0xffffffffu, mi, o);
            if (ov > mv || (ov == mv && oi < mi)) { mv = ov; mi = oi; }
        }
        if ((t & 31) == 0) { rv[t >> 5] = mv; ri[t >> 5] = mi; }
        __syncthreads();
        if (t == 0) {
            #pragma unroll
            for (int w = 1; w < 8; w++)
                if (rv[w] > mv || (rv[w] == mv && ri[w] < mi)) { mv = rv[w]; mi = ri[w]; }
            topIdx[r] = mi;
            s_mi = mi;
        }
        __syncthreads();
        if (r < NTOP - 1) {
            int gm = s_mi;
            if ((gm & 255) == t) {      // only the owner rescans
                wk[gm] = neg_inf();
                lv = neg_inf(); li = 0;
                #pragma unroll
                for (int i = 0; i < 8; i++) {
                    int k = t + i * 256;
                    float v = wk[k];
                    if (v > lv) { lv = v; li = k; }
                }
            }
        }
    }

    if (t < NTOP) {
        int idx = topIdx[t];
        Srow[idx] = g_sh[b * NS + idx];
    }
}

// ============================================================
// K3a: partial column sum of exp over q-segments
// ============================================================
__global__ void __launch_bounds__(256) k_colpart()
{
    int k  = (blockIdx.x * 256 + threadIdx.x) * 4;
    int b  = blockIdx.y;
    int seg = blockIdx.z;
    const float* Sb = g_S + (size_t)b * NS * NS;
    int q0 = seg * QSEG;

    float4 s = make_float4(0.f, 0.f, 0.f, 0.f);
    #pragma unroll 4
    for (int q = q0; q < q0 + QSEG; q++) {
        float4 v = *(const float4*)&Sb[(size_t)q * NS + k];
        s.x += __expf(v.x);
        s.y += __expf(v.y);
        s.z += __expf(v.z);
        s.w += __expf(v.w);
    }
    *(float4*)&g_psum[((size_t)seg * NB + b) * NS + k] = s;
}

// K3b: combine segments -> 1/colsum
__global__ void __launch_bounds__(256) k_colfin()
{
    int i = blockIdx.x * 256 + threadIdx.x;   // b*NS + k
    float s = 0.f;
    #pragma unroll 8
    for (int seg = 0; seg < NSEG; seg++)
        s += g_psum[(size_t)seg * (NB * NS) + i];
    g_cinv[i] = 1.0f / s;
}

// ============================================================
// K4: split-k partial out = sum_k exp(S)*cinv[k]*V[b,k,:]
// 512 threads, tile 64q x 128d, thread 4q x 4d, chunk 32k.
// Register double-buffer prefetch of E and V tiles (LDG->regs
// next chunk issued before computing current chunk from smem).
// 2 blocks/SM (34 KB smem, <=63 regs). grid (NS/64, NB, KSPLIT).
// ============================================================
__global__ void __launch_bounds__(512, 2) k_out(const float* __restrict__ V)
{
    __shared__ ull As2[64][36];                      // dup-packed exp(S)*cinv, 18 KB
    __shared__ __align__(16) float Vs[KC][128];      // 16 KB

    int b  = blockIdx.y;
    int q0 = blockIdx.x * 64;
    int z  = blockIdx.z;
    int t  = threadIdx.x;
    int tx = t & 31;     // d group: d = tx*4
    int ty = t >> 5;     // q group: q = q0 + ty*4 + qq

    const float* Sb = g_S + (size_t)b * NS * NS;
    const float* ci = g_cinv + b * NS;
    const float* Vb = V + (size_t)b * NS * ND;

    // staging maps
    int er  = t >> 3;          // E row 0..63
    int ekg = (t & 7) * 4;     // E col group (4 floats)
    int vr0 = t >> 5,        vc0 = (t & 31) * 4;        // V float4 slots
    int vr1 = (t >> 5) + 16, vc1 = vc0;

    ull acc2[4][2];
    #pragma unroll
    for (int i = 0; i < 4; i++) { acc2[i][0] = 0ull; acc2[i][1] = 0ull; }

    int kbeg = z * KPART;

    // ---- prologue: chunk 0 -> regs ----
    float4 eR = *(const float4*)&Sb[(size_t)(q0 + er) * NS + kbeg + ekg];
    float4 cR = *(const float4*)&ci[kbeg + ekg];
    float4 vRa = *(const float4*)&Vb[(size_t)(kbeg + vr0) * ND + vc0];
    float4 vRb = *(const float4*)&Vb[(size_t)(kbeg + vr1) * ND + vc1];

    #pragma unroll 1
    for (int c = 0; c < KPART / KC; c++) {
        // ---- stage current chunk from regs ----
        {
            float e0 = __expf(eR.x) * cR.x;
            float e1 = __expf(eR.y) * cR.y;
            float e2 = __expf(eR.z) * cR.z;
            float e3 = __expf(eR.w) * cR.w;
            ulonglong2 p0; p0.x = pack2dup(e0); p0.y = pack2dup(e1);
            ulonglong2 p1; p1.x = pack2dup(e2); p1.y = pack2dup(e3);
            *(ulonglong2*)&As2[er][ekg]     = p0;
            *(ulonglong2*)&As2[er][ekg + 2] = p1;
            *(float4*)&Vs[vr0][vc0] = vRa;
            *(float4*)&Vs[vr1][vc1] = vRb;
        }
        __syncthreads();

        // ---- prefetch next chunk into regs (overlaps compute) ----
        if (c + 1 < KPART / KC) {
            int k1 = kbeg + (c + 1) * KC;
            eR  = *(const float4*)&Sb[(size_t)(q0 + er) * NS + k1 + ekg];
            cR  = *(const float4*)&ci[k1 + ekg];
            vRa = *(const float4*)&Vb[(size_t)(k1 + vr0) * ND + vc0];
            vRb = *(const float4*)&Vb[(size_t)(k1 + vr1) * ND + vc1];
        }

        // ---- compute ----
        #pragma unroll
        for (int kk = 0; kk < KC; kk++) {
            ulonglong2 vv = *(const ulonglong2*)&Vs[kk][tx * 4];
            #pragma unroll
            for (int qq = 0; qq < 4; qq++) {
                ull aa = As2[ty * 4 + qq][kk];   // LDS64 broadcast
                fma2(acc2[qq][0], aa, vv.x);
                fma2(acc2[qq][1], aa, vv.y);
            }
        }
        __syncthreads();
    }

    float* po = g_po[z];
    #pragma unroll
    for (int qq = 0; qq < 4; qq++) {
        float4 o;
        unpack2(acc2[qq][0], o.x, o.y);
        unpack2(acc2[qq][1], o.z, o.w);
        *(float4*)&po[(size_t)((b * NS) + q0 + ty * 4 + qq) * ND + tx * 4] = o;
    }
}

// K5: add split-k partials -> final out
__global__ void __launch_bounds__(256) k_add(float* __restrict__ Out)
{
    int p = blockIdx.x * 256 + threadIdx.x;   // float4 index
    float4 a = ((const float4*)g_po[0])[p];
    #pragma unroll
    for (int z = 1; z < KSPLIT; z++) {
        float4 c = ((const float4*)g_po[z])[p];
        a.x += c.x; a.y += c.y; a.z += c.z; a.w += c.w;
    }
    ((float4*)Out)[p] = a;
}

// ============================================================
extern "C" void kernel_launch(void* const* d_in, const int* in_sizes, int n_in,
                              void* d_out, int out_size)
{
    const float* Q   = (const float*)d_in[0];
    const float* K   = (const float*)d_in[1];
    const float* V   = (const float*)d_in[2];
    const int*   VL  = (const int*)d_in[3];
    const float* Wql = (const float*)d_in[4];
    const float* bql = (const float*)d_in[5];
    const float* Wkl = (const float*)d_in[6];
    const float* bkl = (const float*)d_in[7];
    const float* Wqh = (const float*)d_in[8];
    const float* bqh = (const float*)d_in[9];
    const float* Wkh = (const float*)d_in[10];
    const float* bkh = (const float*)d_in[11];
    float* out = (float*)d_out;

    k_proj<<<NB * NS, 64>>>(Q, K, Wql, bql, Wkl, bkl, Wqh, bqh, Wkh, bkh);

    dim3 g2(NS / 128, NS / 32, NB);
    k_scores<<<g2, 256>>>(VL);

    dim3 g2b(NS, NB);
    k_topk<<<g2b, 256>>>();

    dim3 g3(2, NB, NSEG);
    k_colpart<<<g3, 256>>>();
    k_colfin<<<(NB * NS) / 256, 256>>>();

    dim3 g4(NS / 64, NB, KSPLIT);
    k_out<<<g4, 512>>>(V);

    k_add<<<(NB * NS * ND) / 4 / 256, 256>>>(out);
}